// round 6
// baseline (speedup 1.0000x reference)
#include <cuda_runtime.h>
#include <cstdint>

#define DINL __device__ __forceinline__

// ---------------- problem constants ----------------
constexpr int   BHALF = 4096;
constexpr int   NTOT  = 8192;           // 2B rows
constexpr int   DDIM  = 256;            // K
constexpr int   GRID  = 148;            // one exact wave
// alpha^2 = log2(e)/T: y = (z_i . z_j) * alpha^2, exp(s/T) = 2^y
constexpr float QS    = 256.0f;                    // int8 quant scale
constexpr float CONV  = 2.8853901817f / (QS * QS); // alpha^2 / QS^2
constexpr float LN2F  = 0.693147180559945f;

// SMEM: A tile 128x256 s8 (32KB) + two B buffers (32KB) + column scratch
constexpr int SM_A    = 0;
constexpr int SM_B0   = 32768;
constexpr int SM_B1   = 65536;
constexpr int SM_COLS = 98304;                    // 8 warps * 136 floats
constexpr int SMEM_BYTES = 98304 + 8 * 136 * 4;   // 102656

// ---------------- device scratch (no allocation allowed) --------------------
__device__ __align__(16) int8_t g_z[NTOT * DDIM];   // 2 MB
__device__ float g_partial[NTOT];
__device__ float g_pos[NTOT];
__device__ float g_red[64];
__device__ unsigned g_ctr;

// ---------------- PTX helpers ----------------
DINL uint32_t smem_u32(const void* p) {
    uint32_t a;
    asm("{ .reg .u64 t; cvta.to.shared.u64 t, %1; cvt.u32.u64 %0, t; }"
        : "=r"(a) : "l"(p));
    return a;
}
DINL float ex2f(float x) { float r; asm("ex2.approx.f32 %0, %1;" : "=f"(r) : "f"(x)); return r; }
DINL float lg2f(float x) { float r; asm("lg2.approx.f32 %0, %1;" : "=f"(r) : "f"(x)); return r; }

DINL void cp_commit() { asm volatile("cp.async.commit_group;" ::: "memory"); }
DINL void cp_wait0()  { asm volatile("cp.async.wait_group 0;" ::: "memory"); }

DINL void ldsm4(uint32_t& d0, uint32_t& d1, uint32_t& d2, uint32_t& d3, uint32_t addr) {
    asm volatile("ldmatrix.sync.aligned.m8n8.x4.shared.b16 {%0,%1,%2,%3}, [%4];"
                 : "=r"(d0), "=r"(d1), "=r"(d2), "=r"(d3) : "r"(addr));
}
// s8 IMMA, K=32: integer tensor datapath (separate from the FP legacy lane).
DINL void mma16832i(int* c, uint32_t a0, uint32_t a1, uint32_t a2, uint32_t a3,
                    uint32_t b0, uint32_t b1) {
    asm volatile("mma.sync.aligned.m16n8k32.row.col.s32.s8.s8.s32 "
                 "{%0,%1,%2,%3}, {%4,%5,%6,%7}, {%8,%9}, {%0,%1,%2,%3};"
                 : "+r"(c[0]), "+r"(c[1]), "+r"(c[2]), "+r"(c[3])
                 : "r"(a0), "r"(a1), "r"(a2), "r"(a3), "r"(b0), "r"(b1));
}

// Load one 128x256 s8 tile of g_z into SMEM, XOR-swizzled (16B chunk index
// within 256B row XORed with row&7 -> conflict-free ldmatrix).
DINL void load_tile(uint32_t dst, int row0) {
    const char* src = reinterpret_cast<const char*>(g_z) + (size_t)row0 * 256;
    const int t = threadIdx.x;
    #pragma unroll
    for (int it = 0; it < 8; ++it) {
        int lin = it * 256 + t;
        int row = lin >> 4;
        int ch  = lin & 15;
        uint32_t sw = (uint32_t)row * 256u + (uint32_t)((ch ^ (row & 7)) << 4);
        const void* gp = src + (size_t)row * 256 + (size_t)ch * 16;
        asm volatile("cp.async.cg.shared.global [%0], [%1], 16;"
                     :: "r"(dst + sw), "l"(gp) : "memory");
    }
}

// ---------------- fused per-tile compute: 128x128 imma + exp2 + sums --------
DINL void compute_tile(uint32_t a_base, uint32_t b_base, int w, int lane,
                       bool diag, bool pos, int ib, int jb,
                       float& ra0, float& ra1, float* colp) {
    const int mi = lane >> 3, li = lane & 7;
    const int rA = w * 16 + ((mi & 1) << 3) + li;
    const uint32_t aRow = a_base + (uint32_t)rA * 256u;
    const int axr = rA & 7, acp = mi >> 1;
    const int rBo = ((mi >> 1) << 3) + li;
    const int bcp = mi & 1;

    int acc[16][4];
    #pragma unroll
    for (int j = 0; j < 16; ++j) {
        acc[j][0] = 0; acc[j][1] = 0; acc[j][2] = 0; acc[j][3] = 0;
    }

    #pragma unroll
    for (int s = 0; s < 8; ++s) {          // 8 k-steps of K=32 s8
        uint32_t a0, a1, a2, a3;
        ldsm4(a0, a1, a2, a3, aRow + (uint32_t)(((s * 2 + acp) ^ axr) << 4));
        #pragma unroll
        for (int jp = 0; jp < 8; ++jp) {
            int r = jp * 16 + rBo;
            uint32_t b0, b1, b2, b3;
            ldsm4(b0, b1, b2, b3,
                  b_base + (uint32_t)r * 256u +
                  (uint32_t)(((s * 2 + bcp) ^ (r & 7)) << 4));
            mma16832i(acc[2 * jp],     a0, a1, a2, a3, b0, b1);
            mma16832i(acc[2 * jp + 1], a0, a1, a2, a3, b2, b3);
        }
    }

    const int baseRow = w * 16 + (lane >> 2);   // rows baseRow, baseRow+8
    const int baseCol = (lane & 3) * 2;

    if (diag) {
        #pragma unroll
        for (int j = 0; j < 16; ++j) {
            #pragma unroll
            for (int q = 0; q < 4; ++q) {
                int rl = baseRow + ((q & 2) << 2);
                int cl = j * 8 + baseCol + (q & 1);
                float e = ex2f((float)acc[j][q] * CONV);
                if (rl == cl) e = 0.f;                    // mask self-sim
                if (q & 2) ra1 += e; else ra0 += e;
            }
        }
    } else {
        #pragma unroll
        for (int k = 0; k < 32; ++k) colp[k] = 0.f;
        #pragma unroll
        for (int j = 0; j < 16; ++j) {
            float y0 = (float)acc[j][0] * CONV;
            float y1 = (float)acc[j][1] * CONV;
            float y2 = (float)acc[j][2] * CONV;
            float y3 = (float)acc[j][3] * CONV;
            float e0 = ex2f(y0);
            float e1 = ex2f(y1);
            float e2 = ex2f(y2);
            float e3 = ex2f(y3);
            if (pos) {
                int cl0 = j * 8 + baseCol;
                if (cl0     == baseRow)     { g_pos[ib*128+baseRow]   = y0; g_pos[jb*128+baseRow]   = y0; }
                if (cl0 + 1 == baseRow)     { g_pos[ib*128+baseRow]   = y1; g_pos[jb*128+baseRow]   = y1; }
                if (cl0     == baseRow + 8) { g_pos[ib*128+baseRow+8] = y2; g_pos[jb*128+baseRow+8] = y2; }
                if (cl0 + 1 == baseRow + 8) { g_pos[ib*128+baseRow+8] = y3; g_pos[jb*128+baseRow+8] = y3; }
            }
            ra0 += e0 + e1;
            ra1 += e2 + e3;
            colp[j * 2]     += e0 + e2;   // col j*8 + baseCol
            colp[j * 2 + 1] += e1 + e3;   // col j*8 + baseCol + 1
        }
    }
}

DINL void flush_rows(int rb, int w, int lane, float& a0, float& a1) {
    float v0 = a0, v1 = a1;
    v0 += __shfl_xor_sync(0xffffffffu, v0, 1);
    v0 += __shfl_xor_sync(0xffffffffu, v0, 2);
    v1 += __shfl_xor_sync(0xffffffffu, v1, 1);
    v1 += __shfl_xor_sync(0xffffffffu, v1, 2);
    if ((lane & 3) == 0) {
        int r = rb * 128 + w * 16 + (lane >> 2);
        atomicAdd(&g_partial[r],     v0);
        atomicAdd(&g_partial[r + 8], v1);
    }
    a0 = 0.f; a1 = 0.f;
}

// decode (v,k) -> (i,j): virtual row v pairs strip v (64-v tiles) with
// strip 63-v (v+1 tiles): constant 65 tiles per virtual row.
DINL void vk2ij(int v, int k, int& i, int& j) {
    int L = 64 - v;
    if (k < L) { i = v; j = v + k; }
    else       { i = 63 - v; j = i + (k - L); }
}

// ---------------- kernel 1: normalize + quantize to s8 -----------------------
DINL uint32_t pack4(float a, float b, float c, float d, float s) {
    int i0 = __float2int_rn(a * s);
    int i1 = __float2int_rn(b * s);
    int i2 = __float2int_rn(c * s);
    int i3 = __float2int_rn(d * s);
    return (uint32_t)(i0 & 0xFF) | ((uint32_t)(i1 & 0xFF) << 8) |
           ((uint32_t)(i2 & 0xFF) << 16) | ((uint32_t)(i3 & 0xFF) << 24);
}

__global__ void prep_kernel(const float* __restrict__ xi, const float* __restrict__ xj) {
    const int wid = threadIdx.x >> 5, lane = threadIdx.x & 31;
    const int rowA = blockIdx.x * 16 + wid * 2;
    const int rowB = rowA + 1;
    const float* xA = (rowA < BHALF) ? (xi + (size_t)rowA * DDIM)
                                     : (xj + (size_t)(rowA - BHALF) * DDIM);
    const float* xB = (rowB < BHALF) ? (xi + (size_t)rowB * DDIM)
                                     : (xj + (size_t)(rowB - BHALF) * DDIM);
    float4 a0 = *reinterpret_cast<const float4*>(xA + lane * 8);
    float4 a1 = *reinterpret_cast<const float4*>(xA + lane * 8 + 4);
    float4 b0 = *reinterpret_cast<const float4*>(xB + lane * 8);
    float4 b1 = *reinterpret_cast<const float4*>(xB + lane * 8 + 4);
    float sA = a0.x*a0.x + a0.y*a0.y + a0.z*a0.z + a0.w*a0.w
             + a1.x*a1.x + a1.y*a1.y + a1.z*a1.z + a1.w*a1.w;
    float sB = b0.x*b0.x + b0.y*b0.y + b0.z*b0.z + b0.w*b0.w
             + b1.x*b1.x + b1.y*b1.y + b1.z*b1.z + b1.w*b1.w;
    #pragma unroll
    for (int o = 16; o; o >>= 1) {
        sA += __shfl_xor_sync(0xffffffffu, sA, o);
        sB += __shfl_xor_sync(0xffffffffu, sB, o);
    }
    float scA = QS / fmaxf(sqrtf(sA), 1e-12f);
    float scB = QS / fmaxf(sqrtf(sB), 1e-12f);
    uint2 pA, pB;
    pA.x = pack4(a0.x, a0.y, a0.z, a0.w, scA);
    pA.y = pack4(a1.x, a1.y, a1.z, a1.w, scA);
    pB.x = pack4(b0.x, b0.y, b0.z, b0.w, scB);
    pB.y = pack4(b1.x, b1.y, b1.z, b1.w, scB);
    *reinterpret_cast<uint2*>(&g_z[(size_t)rowA * DDIM + lane * 8]) = pA;
    *reinterpret_cast<uint2*>(&g_z[(size_t)rowB * DDIM + lane * 8]) = pB;
    if (lane == 0) { g_partial[rowA] = 0.f; g_partial[rowB] = 0.f; }
    if (rowA == 0 && lane == 1) g_ctr = 0u;
}

// ---------------- kernel 2: triangle-only fused s8 GEMM ---------------------
__global__ void __launch_bounds__(256, 1) gemm_kernel() {
    extern __shared__ char smem[];
    const uint32_t sb = smem_u32(smem);
    const uint32_t A  = sb + SM_A;
    const uint32_t B0 = sb + SM_B0;
    const uint32_t B1 = sb + SM_B1;
    float* smem_cols = reinterpret_cast<float*>(smem + SM_COLS);
    const int tid = threadIdx.x, w = tid >> 5, lane = tid & 31;

    // contiguous range over 2080 triangle tiles: 2080 = 148*14 + 8
    const int c = blockIdx.x;
    const int start = c * 14 + min(c, 8);
    const int count = 14 + (c < 8 ? 1 : 0);

    int v = start / 65, k = start % 65;
    int i, j; vk2ij(v, k, i, j);

    load_tile(A, i * 128);
    load_tile(B0, j * 128);
    cp_commit();
    cp_wait0();
    __syncthreads();

    float ra0 = 0.f, ra1 = 0.f;
    float colp[32];
    int buf = 0;

    for (int n = 0; n < count; ++n) {
        const bool haveNext = (n + 1 < count);
        int nv = v, nk = k + 1;
        if (nk == 65) { nv = v + 1; nk = 0; }
        int ni = 0, nj = 0;
        if (haveNext) vk2ij(nv, nk, ni, nj);

        // prefetch next B into the alternate buffer (overlaps compute)
        if (haveNext) { load_tile(buf ? B0 : B1, nj * 128); cp_commit(); }

        const bool diag = (i == j);
        compute_tile(A, buf ? B1 : B0, w, lane,
                     diag, j == i + 32, i, j, ra0, ra1, colp);

        // column reduce-scatter: 32 -> 4 values per thread over 8-lane groups
        if (!diag) {
            int base16 = 0;
            {
                bool hi = (lane >> 2) & 1;
                #pragma unroll
                for (int t = 0; t < 16; ++t) {
                    float send = hi ? colp[t] : colp[t + 16];
                    float r = __shfl_xor_sync(0xffffffffu, send, 4);
                    colp[t] = (hi ? colp[t + 16] : colp[t]) + r;
                }
                base16 += hi ? 16 : 0;
            }
            {
                bool hi = (lane >> 3) & 1;
                #pragma unroll
                for (int t = 0; t < 8; ++t) {
                    float send = hi ? colp[t] : colp[t + 8];
                    float r = __shfl_xor_sync(0xffffffffu, send, 8);
                    colp[t] = (hi ? colp[t + 8] : colp[t]) + r;
                }
                base16 += hi ? 8 : 0;
            }
            {
                bool hi = (lane >> 4) & 1;
                #pragma unroll
                for (int t = 0; t < 4; ++t) {
                    float send = hi ? colp[t] : colp[t + 4];
                    float r = __shfl_xor_sync(0xffffffffu, send, 16);
                    colp[t] = (hi ? colp[t + 4] : colp[t]) + r;
                }
                base16 += hi ? 4 : 0;
            }
            const int m = lane & 3;
            #pragma unroll
            for (int t = 0; t < 4; ++t) {
                int c16 = base16 + t;
                int col = ((c16 >> 1) << 3) + 2 * m + (c16 & 1);
                smem_cols[w * 136 + col + (col >> 4)] = colp[t];
            }
        }
        __syncthreads();
        if (!diag && tid < 128) {
            const int col = tid + (tid >> 4);
            float s = 0.f;
            #pragma unroll
            for (int w8 = 0; w8 < 8; ++w8) s += smem_cols[w8 * 136 + col];
            atomicAdd(&g_partial[j * 128 + tid], s);
        }

        if (!haveNext || ni != i) flush_rows(i, w, lane, ra0, ra1);

        if (haveNext) {
            if (ni != i) { load_tile(A, ni * 128); cp_commit(); }
            cp_wait0();
            __syncthreads();
        }
        v = nv; k = nk; i = ni; j = nj;
        buf ^= 1;
    }
}

// ---------------- kernel 3: log + positive term + last-block mean ------------
__global__ void final_kernel(float* __restrict__ out) {
    const int r = blockIdx.x * 128 + threadIdx.x;
    // loss_r = ln(denom) - s_pos/T = ln2 * (log2(denom) - y_pos)
    float local = lg2f(g_partial[r]) - g_pos[r];
    #pragma unroll
    for (int o = 16; o; o >>= 1) local += __shfl_xor_sync(0xffffffffu, local, o);
    __shared__ float ws[4];
    __shared__ int isLast;
    if ((threadIdx.x & 31) == 0) ws[threadIdx.x >> 5] = local;
    __syncthreads();
    if (threadIdx.x == 0) {
        g_red[blockIdx.x] = ws[0] + ws[1] + ws[2] + ws[3];
        __threadfence();
        unsigned t = atomicAdd(&g_ctr, 1u);
        isLast = (t == 63u);
    }
    __syncthreads();
    if (isLast && threadIdx.x < 32) {
        __threadfence();
        float t = g_red[threadIdx.x] + g_red[threadIdx.x + 32];
        #pragma unroll
        for (int o = 16; o; o >>= 1) t += __shfl_xor_sync(0xffffffffu, t, o);
        if (threadIdx.x == 0) out[0] = t * (LN2F / (float)NTOT);
    }
}

// ---------------- entry point ----------------
extern "C" void kernel_launch(void* const* d_in, const int* in_sizes, int n_in,
                              void* d_out, int out_size) {
    (void)in_sizes; (void)n_in; (void)out_size;
    const float* xi = (const float*)d_in[0];
    const float* xj = (const float*)d_in[1];

    cudaFuncSetAttribute(gemm_kernel,
                         cudaFuncAttributeMaxDynamicSharedMemorySize, SMEM_BYTES);

    prep_kernel<<<NTOT / 16, 256>>>(xi, xj);
    gemm_kernel<<<GRID, 256, SMEM_BYTES>>>();
    final_kernel<<<64, 128>>>((float*)d_out);
}

// round 7
// speedup vs baseline: 3.0633x; 3.0633x over previous
#include <cuda_runtime.h>
#include <cstdint>

#define DINL __device__ __forceinline__

// ---------------- problem constants ----------------
constexpr int   BHALF = 4096;
constexpr int   NTOT  = 8192;           // 2B rows
constexpr int   DDIM  = 256;            // K
constexpr int   GRID  = 148;            // one exact wave (grid barrier safe)
// alpha = sqrt(log2(e)/T): (a u_i)·(a u_j) = s*log2(e)/T = y, exp(s/T)=2^y
constexpr float ALPHA = 1.6986436f;
constexpr float LN2F  = 0.693147180559945f;

// SMEM: fp8 tiles, A and B both double-buffered: 4 x 32KB = 128KB
constexpr int SM_A0   = 0;
constexpr int SM_A1   = 32768;
constexpr int SM_B0   = 65536;
constexpr int SM_B1   = 98304;
constexpr int SMEM_BYTES = 131072;

// ---------------- device scratch (no allocation allowed) --------------------
__device__ __align__(16) uint8_t g_z[NTOT * DDIM];   // 2 MB, e4m3 (alpha-scaled)
__device__ float g_partial[NTOT];
__device__ float g_pos[NTOT];
__device__ float g_red[64];
__device__ unsigned g_ctr;   // final-reduce counter (reset by prep)
__device__ unsigned g_bar;   // grid barrier counter  (reset by prep)

// ---------------- PTX helpers ----------------
DINL uint32_t smem_u32(const void* p) {
    uint32_t a;
    asm("{ .reg .u64 t; cvta.to.shared.u64 t, %1; cvt.u32.u64 %0, t; }"
        : "=r"(a) : "l"(p));
    return a;
}
DINL float ex2f(float x) { float r; asm("ex2.approx.f32 %0, %1;" : "=f"(r) : "f"(x)); return r; }
DINL float lg2f(float x) { float r; asm("lg2.approx.f32 %0, %1;" : "=f"(r) : "f"(x)); return r; }

DINL void cp_commit() { asm volatile("cp.async.commit_group;" ::: "memory"); }
DINL void cp_wait0()  { asm volatile("cp.async.wait_group 0;" ::: "memory"); }

DINL void ldsm4(uint32_t& d0, uint32_t& d1, uint32_t& d2, uint32_t& d3, uint32_t addr) {
    asm volatile("ldmatrix.sync.aligned.m8n8.x4.shared.b16 {%0,%1,%2,%3}, [%4];"
                 : "=r"(d0), "=r"(d1), "=r"(d2), "=r"(d3) : "r"(addr));
}
// fp8 e4m3 MMA, K=32, f32 accumulators.
DINL void mma16832(float* c, uint32_t a0, uint32_t a1, uint32_t a2, uint32_t a3,
                   uint32_t b0, uint32_t b1) {
    asm volatile("mma.sync.aligned.m16n8k32.row.col.f32.e4m3.e4m3.f32 "
                 "{%0,%1,%2,%3}, {%4,%5,%6,%7}, {%8,%9}, {%0,%1,%2,%3};"
                 : "+f"(c[0]), "+f"(c[1]), "+f"(c[2]), "+f"(c[3])
                 : "r"(a0), "r"(a1), "r"(a2), "r"(a3), "r"(b0), "r"(b1));
}

// Load one 128x256 fp8 tile of g_z into SMEM, XOR-swizzled (16B chunk index
// within 256B row XORed with row&7 -> conflict-free ldmatrix).
DINL void load_tile(uint32_t dst, int row0) {
    const char* src = reinterpret_cast<const char*>(g_z) + (size_t)row0 * 256;
    const int t = threadIdx.x;
    #pragma unroll
    for (int it = 0; it < 8; ++it) {
        int lin = it * 256 + t;
        int row = lin >> 4;
        int ch  = lin & 15;
        uint32_t sw = (uint32_t)row * 256u + (uint32_t)((ch ^ (row & 7)) << 4);
        const void* gp = src + (size_t)row * 256 + (size_t)ch * 16;
        asm volatile("cp.async.cg.shared.global [%0], [%1], 16;"
                     :: "r"(dst + sw), "l"(gp) : "memory");
    }
}

// ---------------- fused per-tile compute: 128x128 mma + exp2 + sums ---------
DINL void compute_tile(uint32_t a_base, uint32_t b_base, int w, int lane,
                       bool diag, bool pos, int ib, int jb,
                       float& ra0, float& ra1, float* colp) {
    const int mi = lane >> 3, li = lane & 7;
    const int rA = w * 16 + ((mi & 1) << 3) + li;
    const uint32_t aRow = a_base + (uint32_t)rA * 256u;
    const int axr = rA & 7, acp = mi >> 1;
    const int rBo = ((mi >> 1) << 3) + li;
    const int bcp = mi & 1;

    float acc[16][4];
    #pragma unroll
    for (int j = 0; j < 16; ++j) {
        acc[j][0] = 0.f; acc[j][1] = 0.f; acc[j][2] = 0.f; acc[j][3] = 0.f;
    }

    #pragma unroll
    for (int s = 0; s < 8; ++s) {          // 8 k-steps of K=32 fp8
        uint32_t a0, a1, a2, a3;
        ldsm4(a0, a1, a2, a3, aRow + (uint32_t)(((s * 2 + acp) ^ axr) << 4));
        #pragma unroll
        for (int jp = 0; jp < 8; ++jp) {
            int r = jp * 16 + rBo;
            uint32_t b0, b1, b2, b3;
            ldsm4(b0, b1, b2, b3,
                  b_base + (uint32_t)r * 256u +
                  (uint32_t)(((s * 2 + bcp) ^ (r & 7)) << 4));
            mma16832(acc[2 * jp],     a0, a1, a2, a3, b0, b1);
            mma16832(acc[2 * jp + 1], a0, a1, a2, a3, b2, b3);
        }
    }

    const int baseRow = w * 16 + (lane >> 2);   // rows baseRow, baseRow+8
    const int baseCol = (lane & 3) * 2;

    if (diag) {
        #pragma unroll
        for (int j = 0; j < 16; ++j) {
            #pragma unroll
            for (int q = 0; q < 4; ++q) {
                int rl = baseRow + ((q & 2) << 2);
                int cl = j * 8 + baseCol + (q & 1);
                float e = ex2f(acc[j][q]);
                if (rl == cl) e = 0.f;                    // mask self-sim
                if (q & 2) ra1 += e; else ra0 += e;
            }
        }
    } else {
        #pragma unroll
        for (int k = 0; k < 32; ++k) colp[k] = 0.f;
        #pragma unroll
        for (int j = 0; j < 16; ++j) {
            float e0 = ex2f(acc[j][0]);
            float e1 = ex2f(acc[j][1]);
            float e2 = ex2f(acc[j][2]);
            float e3 = ex2f(acc[j][3]);
            if (pos) {
                int cl0 = j * 8 + baseCol;
                if (cl0     == baseRow)     { g_pos[ib*128+baseRow]   = acc[j][0]; g_pos[jb*128+baseRow]   = acc[j][0]; }
                if (cl0 + 1 == baseRow)     { g_pos[ib*128+baseRow]   = acc[j][1]; g_pos[jb*128+baseRow]   = acc[j][1]; }
                if (cl0     == baseRow + 8) { g_pos[ib*128+baseRow+8] = acc[j][2]; g_pos[jb*128+baseRow+8] = acc[j][2]; }
                if (cl0 + 1 == baseRow + 8) { g_pos[ib*128+baseRow+8] = acc[j][3]; g_pos[jb*128+baseRow+8] = acc[j][3]; }
            }
            ra0 += e0 + e1;
            ra1 += e2 + e3;
            colp[j * 2]     += e0 + e2;   // col j*8 + baseCol
            colp[j * 2 + 1] += e1 + e3;   // col j*8 + baseCol + 1
        }
    }
}

DINL void flush_rows(int rb, int w, int lane, float& a0, float& a1) {
    float v0 = a0, v1 = a1;
    v0 += __shfl_xor_sync(0xffffffffu, v0, 1);
    v0 += __shfl_xor_sync(0xffffffffu, v0, 2);
    v1 += __shfl_xor_sync(0xffffffffu, v1, 1);
    v1 += __shfl_xor_sync(0xffffffffu, v1, 2);
    if ((lane & 3) == 0) {
        int r = rb * 128 + w * 16 + (lane >> 2);
        atomicAdd(&g_partial[r],     v0);
        atomicAdd(&g_partial[r + 8], v1);
    }
    a0 = 0.f; a1 = 0.f;
}

// decode (v,k) -> (i,j): virtual row v pairs strip v (64-v tiles) with
// strip 63-v (v+1 tiles): constant 65 tiles per virtual row.
DINL void vk2ij(int v, int k, int& i, int& j) {
    int L = 64 - v;
    if (k < L) { i = v; j = v + k; }
    else       { i = 63 - v; j = i + (k - L); }
}

// ---------------- kernel 1: normalize + pre-scale + e4m3 cast ----------------
__global__ void prep_kernel(const float* __restrict__ xi, const float* __restrict__ xj) {
    const int wid = threadIdx.x >> 5, lane = threadIdx.x & 31;
    const int r0 = (blockIdx.x * 8 + wid) * 4;      // 4 rows per warp

    float4 va[4], vb[4];
    float s[4];
    #pragma unroll
    for (int rr = 0; rr < 4; ++rr) {
        int row = r0 + rr;
        const float* x = (row < BHALF) ? (xi + (size_t)row * DDIM)
                                       : (xj + (size_t)(row - BHALF) * DDIM);
        va[rr] = *reinterpret_cast<const float4*>(x + lane * 8);
        vb[rr] = *reinterpret_cast<const float4*>(x + lane * 8 + 4);
    }
    #pragma unroll
    for (int rr = 0; rr < 4; ++rr)
        s[rr] = va[rr].x*va[rr].x + va[rr].y*va[rr].y + va[rr].z*va[rr].z + va[rr].w*va[rr].w
              + vb[rr].x*vb[rr].x + vb[rr].y*vb[rr].y + vb[rr].z*vb[rr].z + vb[rr].w*vb[rr].w;
    #pragma unroll
    for (int o = 16; o; o >>= 1) {
        s[0] += __shfl_xor_sync(0xffffffffu, s[0], o);
        s[1] += __shfl_xor_sync(0xffffffffu, s[1], o);
        s[2] += __shfl_xor_sync(0xffffffffu, s[2], o);
        s[3] += __shfl_xor_sync(0xffffffffu, s[3], o);
    }
    #pragma unroll
    for (int rr = 0; rr < 4; ++rr) {
        float sc = ALPHA / fmaxf(sqrtf(s[rr]), 1e-12f);
        uint16_t p0, p1, p2, p3;
        asm("cvt.rn.satfinite.e4m3x2.f32 %0, %1, %2;" : "=h"(p0) : "f"(va[rr].y*sc), "f"(va[rr].x*sc));
        asm("cvt.rn.satfinite.e4m3x2.f32 %0, %1, %2;" : "=h"(p1) : "f"(va[rr].w*sc), "f"(va[rr].z*sc));
        asm("cvt.rn.satfinite.e4m3x2.f32 %0, %1, %2;" : "=h"(p2) : "f"(vb[rr].y*sc), "f"(vb[rr].x*sc));
        asm("cvt.rn.satfinite.e4m3x2.f32 %0, %1, %2;" : "=h"(p3) : "f"(vb[rr].w*sc), "f"(vb[rr].z*sc));
        uint2 pk;
        pk.x = (uint32_t)p0 | ((uint32_t)p1 << 16);
        pk.y = (uint32_t)p2 | ((uint32_t)p3 << 16);
        *reinterpret_cast<uint2*>(&g_z[(size_t)(r0 + rr) * DDIM + lane * 8]) = pk;
    }
    if (lane < 4) g_partial[r0 + lane] = 0.f;       // zero accumulators
    if (blockIdx.x == 0 && threadIdx.x == 0) { g_ctr = 0u; g_bar = 0u; }
}

// ---------------- kernel 2: triangle fused GEMM + in-kernel final ------------
__global__ void __launch_bounds__(256, 1) gemm_kernel(float* __restrict__ out) {
    extern __shared__ char smem[];
    const uint32_t sb = smem_u32(smem);
    const uint32_t Ab[2] = { sb + SM_A0, sb + SM_A1 };
    const uint32_t Bb[2] = { sb + SM_B0, sb + SM_B1 };
    const int tid = threadIdx.x, w = tid >> 5, lane = tid & 31;

    // contiguous range over 2080 triangle tiles: 2080 = 148*14 + 8
    const int c = blockIdx.x;
    const int start = c * 14 + min(c, 8);
    const int count = 14 + (c < 8 ? 1 : 0);

    int v = start / 65, k = start % 65;
    int i, j; vk2ij(v, k, i, j);

    load_tile(Ab[0], i * 128);
    load_tile(Bb[0], j * 128);
    cp_commit();
    cp_wait0();
    __syncthreads();

    float ra0 = 0.f, ra1 = 0.f;
    float colp[32];
    int abuf = 0, bbuf = 0;

    for (int n = 0; n < count; ++n) {
        const bool haveNext = (n + 1 < count);
        int nv = v, nk = k + 1;
        if (nk == 65) { nv = v + 1; nk = 0; }
        int ni = i, nj = j;
        if (haveNext) vk2ij(nv, nk, ni, nj);
        const bool aswap = haveNext && (ni != i);

        // prefetch next B (and A at row-block boundaries) -> alternate buffers
        if (haveNext) {
            load_tile(Bb[bbuf ^ 1], nj * 128);
            if (aswap) load_tile(Ab[abuf ^ 1], ni * 128);
            cp_commit();
        }

        const bool diag = (i == j);
        compute_tile(Ab[abuf], Bb[bbuf], w, lane,
                     diag, j == i + 32, i, j, ra0, ra1, colp);

        // column reduce-scatter: 32 -> 4 per thread, then direct REDG atomics
        if (!diag) {
            int base16 = 0;
            {
                bool hi = (lane >> 2) & 1;
                #pragma unroll
                for (int t = 0; t < 16; ++t) {
                    float send = hi ? colp[t] : colp[t + 16];
                    float r = __shfl_xor_sync(0xffffffffu, send, 4);
                    colp[t] = (hi ? colp[t + 16] : colp[t]) + r;
                }
                base16 += hi ? 16 : 0;
            }
            {
                bool hi = (lane >> 3) & 1;
                #pragma unroll
                for (int t = 0; t < 8; ++t) {
                    float send = hi ? colp[t] : colp[t + 8];
                    float r = __shfl_xor_sync(0xffffffffu, send, 8);
                    colp[t] = (hi ? colp[t + 8] : colp[t]) + r;
                }
                base16 += hi ? 8 : 0;
            }
            {
                bool hi = (lane >> 4) & 1;
                #pragma unroll
                for (int t = 0; t < 4; ++t) {
                    float send = hi ? colp[t] : colp[t + 4];
                    float r = __shfl_xor_sync(0xffffffffu, send, 16);
                    colp[t] = (hi ? colp[t + 4] : colp[t]) + r;
                }
                base16 += hi ? 4 : 0;
            }
            const int m = lane & 3;
            #pragma unroll
            for (int t = 0; t < 4; ++t) {
                int c16 = base16 + t;
                int col = ((c16 >> 1) << 3) + 2 * m + (c16 & 1);
                atomicAdd(&g_partial[j * 128 + col], colp[t]);
            }
        }

        if (!haveNext || ni != i) flush_rows(i, w, lane, ra0, ra1);

        if (haveNext) {
            cp_wait0();
            __syncthreads();    // next tiles ready; all warps done with old bufs
        }
        v = nv; k = nk; i = ni; j = nj;
        bbuf ^= 1;
        if (aswap) abuf ^= 1;
    }

    // ---- grid barrier: all 148 CTAs resident (one wave) ----
    __syncthreads();
    if (tid == 0) {
        __threadfence();
        atomicAdd(&g_bar, 1u);
        volatile unsigned* p = &g_bar;
        while (*p < (unsigned)GRID) { }
        __threadfence();
    }
    __syncthreads();

    // ---- final phase: per-row loss, then last-block mean ----
    if (c < 64 && tid < 128) {
        const int r = c * 128 + tid;
        // loss_r = ln(denom) - s_pos/T = ln2 * (log2(denom) - y_pos)
        float local = lg2f(g_partial[r]) - g_pos[r];
        #pragma unroll
        for (int o = 16; o; o >>= 1) local += __shfl_xor_sync(0xffffffffu, local, o);
        __shared__ float ws[4];
        __shared__ int isLast;
        if ((tid & 31) == 0) ws[tid >> 5] = local;
        __syncwarp();
        asm volatile("bar.sync 1, 128;" ::: "memory");
        if (tid == 0) {
            g_red[c] = ws[0] + ws[1] + ws[2] + ws[3];
            __threadfence();
            unsigned t = atomicAdd(&g_ctr, 1u);
            isLast = (t == 63u);
        }
        asm volatile("bar.sync 1, 128;" ::: "memory");
        if (isLast && tid < 32) {
            __threadfence();
            float t = g_red[tid] + g_red[tid + 32];
            #pragma unroll
            for (int o = 16; o; o >>= 1) t += __shfl_xor_sync(0xffffffffu, t, o);
            if (tid == 0) out[0] = t * (LN2F / (float)NTOT);
        }
    }
}

// ---------------- entry point ----------------
extern "C" void kernel_launch(void* const* d_in, const int* in_sizes, int n_in,
                              void* d_out, int out_size) {
    (void)in_sizes; (void)n_in; (void)out_size;
    const float* xi = (const float*)d_in[0];
    const float* xj = (const float*)d_in[1];

    cudaFuncSetAttribute(gemm_kernel,
                         cudaFuncAttributeMaxDynamicSharedMemorySize, SMEM_BYTES);

    prep_kernel<<<NTOT / 32, 256>>>(xi, xj);
    gemm_kernel<<<GRID, 256, SMEM_BYTES>>>((float*)d_out);
}

// round 8
// speedup vs baseline: 3.2456x; 1.0595x over previous
#include <cuda_runtime.h>
#include <cstdint>

#define DINL __device__ __forceinline__

// ---------------- problem constants ----------------
constexpr int   BHALF = 4096;
constexpr int   NTOT  = 8192;           // 2B rows
constexpr int   DDIM  = 256;            // K
constexpr int   GRID  = 148;            // one exact wave (grid barrier safe)
// alpha = sqrt(log2(e)/T): (a u_i)·(a u_j) = s*log2(e)/T = y, exp(s/T)=2^y
constexpr float ALPHA = 1.6986436f;
constexpr float LN2F  = 0.693147180559945f;

// SMEM: fp8 tiles, A and B both double-buffered: 4 x 32KB = 128KB
constexpr int SM_A0   = 0;
constexpr int SM_A1   = 32768;
constexpr int SM_B0   = 65536;
constexpr int SM_B1   = 98304;
constexpr int SMEM_BYTES = 131072;

// ---------------- device scratch (no allocation allowed) --------------------
__device__ __align__(16) uint8_t g_z[NTOT * DDIM];   // 2 MB, e4m3 (alpha-scaled)
__device__ float g_partial[NTOT];
__device__ float g_pos[NTOT];
__device__ float g_red[64];
__device__ unsigned g_ctr;   // final-reduce counter (reset by prep)
__device__ unsigned g_bar;   // grid barrier counter  (reset by prep)

// ---------------- PTX helpers ----------------
DINL uint32_t smem_u32(const void* p) {
    uint32_t a;
    asm("{ .reg .u64 t; cvta.to.shared.u64 t, %1; cvt.u32.u64 %0, t; }"
        : "=r"(a) : "l"(p));
    return a;
}
DINL float ex2f(float x) { float r; asm("ex2.approx.f32 %0, %1;" : "=f"(r) : "f"(x)); return r; }
DINL float lg2f(float x) { float r; asm("lg2.approx.f32 %0, %1;" : "=f"(r) : "f"(x)); return r; }

DINL void cp_commit() { asm volatile("cp.async.commit_group;" ::: "memory"); }
DINL void cp_wait0()  { asm volatile("cp.async.wait_group 0;" ::: "memory"); }

DINL void ldsm4(uint32_t& d0, uint32_t& d1, uint32_t& d2, uint32_t& d3, uint32_t addr) {
    asm volatile("ldmatrix.sync.aligned.m8n8.x4.shared.b16 {%0,%1,%2,%3}, [%4];"
                 : "=r"(d0), "=r"(d1), "=r"(d2), "=r"(d3) : "r"(addr));
}
// fp8 e4m3 MMA, K=32, f32 accumulators.
DINL void mma16832(float* c, uint32_t a0, uint32_t a1, uint32_t a2, uint32_t a3,
                   uint32_t b0, uint32_t b1) {
    asm volatile("mma.sync.aligned.m16n8k32.row.col.f32.e4m3.e4m3.f32 "
                 "{%0,%1,%2,%3}, {%4,%5,%6,%7}, {%8,%9}, {%0,%1,%2,%3};"
                 : "+f"(c[0]), "+f"(c[1]), "+f"(c[2]), "+f"(c[3])
                 : "r"(a0), "r"(a1), "r"(a2), "r"(a3), "r"(b0), "r"(b1));
}

// Load one 128x256 fp8 tile of g_z into SMEM, XOR-swizzled (16B chunk index
// within 256B row XORed with row&7 -> conflict-free ldmatrix). 512 threads.
DINL void load_tile(uint32_t dst, int row0) {
    const char* src = reinterpret_cast<const char*>(g_z) + (size_t)row0 * 256;
    const int t = threadIdx.x;
    #pragma unroll
    for (int it = 0; it < 4; ++it) {
        int lin = it * 512 + t;
        int row = lin >> 4;
        int ch  = lin & 15;
        uint32_t sw = (uint32_t)row * 256u + (uint32_t)((ch ^ (row & 7)) << 4);
        const void* gp = src + (size_t)row * 256 + (size_t)ch * 16;
        asm volatile("cp.async.cg.shared.global [%0], [%1], 16;"
                     :: "r"(dst + sw), "l"(gp) : "memory");
    }
}

// ---------------- fused per-tile compute ------------------------------------
// 16 warps: warp w -> rows [rg*16, rg*16+16), cols [cg*64, cg*64+64),
// rg = w>>1, cg = w&1. acc = 32 regs/thread, colp = 16 floats/thread.
DINL void compute_tile(uint32_t a_base, uint32_t b_base, int rg, int cg, int lane,
                       bool diag, bool pos, int ib, int jb,
                       float& ra0, float& ra1, float* colp) {
    const int mi = lane >> 3, li = lane & 7;
    const int rA = rg * 16 + ((mi & 1) << 3) + li;
    const uint32_t aRow = a_base + (uint32_t)rA * 256u;
    const int axr = rA & 7, acp = mi >> 1;
    const int rBo = ((mi >> 1) << 3) + li;
    const int bcp = mi & 1;

    uint32_t bBase[4];
    int bxr[4];
    #pragma unroll
    for (int jp = 0; jp < 4; ++jp) {
        int r = cg * 64 + jp * 16 + rBo;
        bBase[jp] = b_base + (uint32_t)r * 256u;
        bxr[jp] = r & 7;
    }

    float acc[8][4];
    #pragma unroll
    for (int j = 0; j < 8; ++j) {
        acc[j][0] = 0.f; acc[j][1] = 0.f; acc[j][2] = 0.f; acc[j][3] = 0.f;
    }

    #pragma unroll
    for (int s = 0; s < 8; ++s) {          // 8 k-steps of K=32 fp8
        uint32_t a0, a1, a2, a3;
        ldsm4(a0, a1, a2, a3, aRow + (uint32_t)(((s * 2 + acp) ^ axr) << 4));
        #pragma unroll
        for (int jp = 0; jp < 4; ++jp) {
            uint32_t b0, b1, b2, b3;
            ldsm4(b0, b1, b2, b3, bBase[jp] + (uint32_t)(((s * 2 + bcp) ^ bxr[jp]) << 4));
            mma16832(acc[2 * jp],     a0, a1, a2, a3, b0, b1);
            mma16832(acc[2 * jp + 1], a0, a1, a2, a3, b2, b3);
        }
    }

    const int baseRow = rg * 16 + (lane >> 2);       // rows baseRow, baseRow+8
    const int baseCol = cg * 64 + (lane & 3) * 2;    // first of 2 cols per acc

    if (diag) {
        #pragma unroll
        for (int j = 0; j < 8; ++j) {
            #pragma unroll
            for (int q = 0; q < 4; ++q) {
                int rl = baseRow + ((q & 2) << 2);
                int cl = baseCol + j * 8 + (q & 1);
                float e = ex2f(acc[j][q]);
                if (rl == cl) e = 0.f;                    // mask self-sim
                if (q & 2) ra1 += e; else ra0 += e;
            }
        }
    } else {
        #pragma unroll
        for (int k = 0; k < 16; ++k) colp[k] = 0.f;
        #pragma unroll
        for (int j = 0; j < 8; ++j) {
            float e0 = ex2f(acc[j][0]);
            float e1 = ex2f(acc[j][1]);
            float e2 = ex2f(acc[j][2]);
            float e3 = ex2f(acc[j][3]);
            if (pos) {
                int cl0 = baseCol + j * 8;
                if (cl0     == baseRow)     { g_pos[ib*128+baseRow]   = acc[j][0]; g_pos[jb*128+baseRow]   = acc[j][0]; }
                if (cl0 + 1 == baseRow)     { g_pos[ib*128+baseRow]   = acc[j][1]; g_pos[jb*128+baseRow]   = acc[j][1]; }
                if (cl0     == baseRow + 8) { g_pos[ib*128+baseRow+8] = acc[j][2]; g_pos[jb*128+baseRow+8] = acc[j][2]; }
                if (cl0 + 1 == baseRow + 8) { g_pos[ib*128+baseRow+8] = acc[j][3]; g_pos[jb*128+baseRow+8] = acc[j][3]; }
            }
            ra0 += e0 + e1;
            ra1 += e2 + e3;
            colp[j * 2]     += e0 + e2;   // col baseCol + j*8
            colp[j * 2 + 1] += e1 + e3;   // col baseCol + j*8 + 1
        }
    }
}

DINL void flush_rows(int rb, int rg, int lane, float& a0, float& a1) {
    float v0 = a0, v1 = a1;
    v0 += __shfl_xor_sync(0xffffffffu, v0, 1);
    v0 += __shfl_xor_sync(0xffffffffu, v0, 2);
    v1 += __shfl_xor_sync(0xffffffffu, v1, 1);
    v1 += __shfl_xor_sync(0xffffffffu, v1, 2);
    if ((lane & 3) == 0) {
        int r = rb * 128 + rg * 16 + (lane >> 2);
        atomicAdd(&g_partial[r],     v0);
        atomicAdd(&g_partial[r + 8], v1);
    }
    a0 = 0.f; a1 = 0.f;
}

// decode (v,k) -> (i,j): virtual row v pairs strip v (64-v tiles) with
// strip 63-v (v+1 tiles): constant 65 tiles per virtual row.
DINL void vk2ij(int v, int k, int& i, int& j) {
    int L = 64 - v;
    if (k < L) { i = v; j = v + k; }
    else       { i = 63 - v; j = i + (k - L); }
}

// ---------------- kernel 1: normalize + pre-scale + e4m3 cast ----------------
__global__ void prep_kernel(const float* __restrict__ xi, const float* __restrict__ xj) {
    const int wid = threadIdx.x >> 5, lane = threadIdx.x & 31;
    const int row = blockIdx.x * 8 + wid;
    const float* x = (row < BHALF) ? (xi + (size_t)row * DDIM)
                                   : (xj + (size_t)(row - BHALF) * DDIM);
    float4 v0 = *reinterpret_cast<const float4*>(x + lane * 8);
    float4 v1 = *reinterpret_cast<const float4*>(x + lane * 8 + 4);
    float s = v0.x*v0.x + v0.y*v0.y + v0.z*v0.z + v0.w*v0.w
            + v1.x*v1.x + v1.y*v1.y + v1.z*v1.z + v1.w*v1.w;
    #pragma unroll
    for (int o = 16; o; o >>= 1) s += __shfl_xor_sync(0xffffffffu, s, o);
    float sc = ALPHA / fmaxf(sqrtf(s), 1e-12f);
    uint16_t p0, p1, p2, p3;
    asm("cvt.rn.satfinite.e4m3x2.f32 %0, %1, %2;" : "=h"(p0) : "f"(v0.y*sc), "f"(v0.x*sc));
    asm("cvt.rn.satfinite.e4m3x2.f32 %0, %1, %2;" : "=h"(p1) : "f"(v0.w*sc), "f"(v0.z*sc));
    asm("cvt.rn.satfinite.e4m3x2.f32 %0, %1, %2;" : "=h"(p2) : "f"(v1.y*sc), "f"(v1.x*sc));
    asm("cvt.rn.satfinite.e4m3x2.f32 %0, %1, %2;" : "=h"(p3) : "f"(v1.w*sc), "f"(v1.z*sc));
    uint2 pk;
    pk.x = (uint32_t)p0 | ((uint32_t)p1 << 16);
    pk.y = (uint32_t)p2 | ((uint32_t)p3 << 16);
    *reinterpret_cast<uint2*>(&g_z[(size_t)row * DDIM + lane * 8]) = pk;
    if (lane == 0) g_partial[row] = 0.f;   // zero accumulators every launch
    if (row == 0 && lane == 1) { g_ctr = 0u; g_bar = 0u; }
}

// ---------------- kernel 2: triangle fused GEMM + in-kernel final ------------
__global__ void __launch_bounds__(512, 1) gemm_kernel(float* __restrict__ out) {
    extern __shared__ char smem[];
    const uint32_t sb = smem_u32(smem);
    const uint32_t Ab[2] = { sb + SM_A0, sb + SM_A1 };
    const uint32_t Bb[2] = { sb + SM_B0, sb + SM_B1 };
    const int tid = threadIdx.x, w = tid >> 5, lane = tid & 31;
    const int rg = w >> 1, cg = w & 1;

    // contiguous range over 2080 triangle tiles: 2080 = 148*14 + 8
    const int c = blockIdx.x;
    const int start = c * 14 + min(c, 8);
    const int count = 14 + (c < 8 ? 1 : 0);

    int v = start / 65, k = start % 65;
    int i, j; vk2ij(v, k, i, j);

    load_tile(Ab[0], i * 128);
    load_tile(Bb[0], j * 128);
    cp_commit();
    cp_wait0();
    __syncthreads();

    float ra0 = 0.f, ra1 = 0.f;
    float colp[16];
    int abuf = 0, bbuf = 0;

    for (int n = 0; n < count; ++n) {
        const bool haveNext = (n + 1 < count);
        int nv = v, nk = k + 1;
        if (nk == 65) { nv = v + 1; nk = 0; }
        int ni = i, nj = j;
        if (haveNext) vk2ij(nv, nk, ni, nj);
        const bool aswap = haveNext && (ni != i);

        // prefetch next B (and A at row-block boundaries) -> alternate buffers
        if (haveNext) {
            load_tile(Bb[bbuf ^ 1], nj * 128);
            if (aswap) load_tile(Ab[abuf ^ 1], ni * 128);
            cp_commit();
        }

        const bool diag = (i == j);
        compute_tile(Ab[abuf], Bb[bbuf], rg, cg, lane,
                     diag, j == i + 32, i, j, ra0, ra1, colp);

        // column reduce-scatter: 16 -> 2 per thread, then direct atomics
        if (!diag) {
            int base8 = 0;
            {
                bool hi = (lane >> 2) & 1;
                #pragma unroll
                for (int t = 0; t < 8; ++t) {
                    float send = hi ? colp[t] : colp[t + 8];
                    float r = __shfl_xor_sync(0xffffffffu, send, 4);
                    colp[t] = (hi ? colp[t + 8] : colp[t]) + r;
                }
                base8 += hi ? 8 : 0;
            }
            {
                bool hi = (lane >> 3) & 1;
                #pragma unroll
                for (int t = 0; t < 4; ++t) {
                    float send = hi ? colp[t] : colp[t + 4];
                    float r = __shfl_xor_sync(0xffffffffu, send, 8);
                    colp[t] = (hi ? colp[t + 4] : colp[t]) + r;
                }
                base8 += hi ? 4 : 0;
            }
            {
                bool hi = (lane >> 4) & 1;
                #pragma unroll
                for (int t = 0; t < 2; ++t) {
                    float send = hi ? colp[t] : colp[t + 2];
                    float r = __shfl_xor_sync(0xffffffffu, send, 16);
                    colp[t] = (hi ? colp[t + 2] : colp[t]) + r;
                }
                base8 += hi ? 2 : 0;
            }
            const int m = lane & 3;
            #pragma unroll
            for (int t = 0; t < 2; ++t) {
                int c16 = base8 + t;
                int col = cg * 64 + ((c16 >> 1) << 3) + 2 * m + (c16 & 1);
                atomicAdd(&g_partial[j * 128 + col], colp[t]);
            }
        }

        if (!haveNext || ni != i) flush_rows(i, rg, lane, ra0, ra1);

        if (haveNext) {
            cp_wait0();
            __syncthreads();    // next tiles ready; all warps done with old bufs
        }
        v = nv; k = nk; i = ni; j = nj;
        bbuf ^= 1;
        if (aswap) abuf ^= 1;
    }

    // ---- grid barrier: all 148 CTAs resident (one wave) ----
    __syncthreads();
    if (tid == 0) {
        __threadfence();
        atomicAdd(&g_bar, 1u);
        volatile unsigned* p = &g_bar;
        while (*p < (unsigned)GRID) { }
        __threadfence();
    }
    __syncthreads();

    // ---- final phase: per-row loss, then last-block mean ----
    if (c < 64 && tid < 128) {
        const int r = c * 128 + tid;
        // loss_r = ln(denom) - s_pos/T = ln2 * (log2(denom) - y_pos)
        float local = lg2f(g_partial[r]) - g_pos[r];
        #pragma unroll
        for (int o = 16; o; o >>= 1) local += __shfl_xor_sync(0xffffffffu, local, o);
        __shared__ float ws[4];
        __shared__ int isLast;
        if ((tid & 31) == 0) ws[tid >> 5] = local;
        __syncwarp();
        asm volatile("bar.sync 1, 128;" ::: "memory");
        if (tid == 0) {
            g_red[c] = ws[0] + ws[1] + ws[2] + ws[3];
            __threadfence();
            unsigned t = atomicAdd(&g_ctr, 1u);
            isLast = (t == 63u);
        }
        asm volatile("bar.sync 1, 128;" ::: "memory");
        if (isLast && tid < 32) {
            __threadfence();
            float t = g_red[tid] + g_red[tid + 32];
            #pragma unroll
            for (int o = 16; o; o >>= 1) t += __shfl_xor_sync(0xffffffffu, t, o);
            if (tid == 0) out[0] = t * (LN2F / (float)NTOT);
        }
    }
}

// ---------------- entry point ----------------
extern "C" void kernel_launch(void* const* d_in, const int* in_sizes, int n_in,
                              void* d_out, int out_size) {
    (void)in_sizes; (void)n_in; (void)out_size;
    const float* xi = (const float*)d_in[0];
    const float* xj = (const float*)d_in[1];

    cudaFuncSetAttribute(gemm_kernel,
                         cudaFuncAttributeMaxDynamicSharedMemorySize, SMEM_BYTES);

    prep_kernel<<<NTOT / 8, 256>>>(xi, xj);
    gemm_kernel<<<GRID, 512, SMEM_BYTES>>>((float*)d_out);
}